// round 10
// baseline (speedup 1.0000x reference)
#include <cuda_runtime.h>
#include <math.h>

// Problem constants
#define BB 4
#define CC 128
#define HH 240
#define WW 320
#define NN 1024
#define NPTS (BB * NN)
#define NSLICE 4
#define SLICE_C 32          // channels per slice
#define S2_BLOCKS 128       // stage-2: 128 blocks x 32 threads, 1 point/thread

// Per-(point,slice) partials: 9 floats packed in 3 float4 (AoS — proven layout)
__device__ float4 g_part[NPTS * NSLICE * 3];
// Per-block partials for the final sum (S2_BLOCKS stage-2 blocks)
__device__ double g_bp_e1[S2_BLOCKS];
__device__ double g_bp_ld[S2_BLOCKS];
__device__ unsigned int g_count = 0;

__device__ __forceinline__ float warp_sum(float v) {
#pragma unroll
    for (int o = 16; o; o >>= 1) v += __shfl_xor_sync(0xffffffffu, v, o);
    return v;
}

__device__ __forceinline__ double warp_sum_d(double v) {
#pragma unroll
    for (int o = 16; o; o >>= 1) v += __shfl_xor_sync(0xffffffffu, v, o);
    return v;
}

// ---------------- Stage 1: gather + per-(point,slice) partial sums ----------------
// Grid: NSLICE * (NPTS/4) blocks of 128 threads, slice-major.
// Block handles 4 points x one 32-channel slice; each warp owns one point.
__global__ __launch_bounds__(128) void gnloss_stage1(
    const float* __restrict__ Fa, const float* __restrict__ Fb,
    const float* __restrict__ ma, const float* __restrict__ mb,
    const float* __restrict__ noise)
{
    const int bid   = blockIdx.x;
    const int slice = bid >> 10;           // 0..3  (slice-major ordering)
    const int pg    = bid & 1023;          // point group
    const int w     = threadIdx.x >> 5;
    const int lane  = threadIdx.x & 31;
    const int p     = pg * 4 + w;          // point 0..4095
    const int b     = p >> 10;
    const int c     = slice * SLICE_C + lane;

    const float invL = 1.0f / 8.0f;
    const float2 mav = ((const float2*)ma)[p];
    const float2 mbv = ((const float2*)mb)[p];
    const float2 nzv = ((const float2*)noise)[p];
    const float xa = mav.x * invL, ya = mav.y * invL;
    const float xs = 2.0f * nzv.x - 1.0f + mbv.x * invL;
    const float ys = 2.0f * nzv.y - 1.0f + mbv.y * invL;

    // ---- f_t: bilinear sample of F_a ----
    const float* pa = Fa + (size_t)(b * CC + c) * (HH * WW);
    float fx0 = floorf(xa), fy0 = floorf(ya);
    float wxa = xa - fx0,  wya = ya - fy0;
    int ax0 = min(max((int)fx0, 0), WW - 1);
    int ax1 = min(ax0 + 1, WW - 1);
    int ay0 = min(max((int)fy0, 0), HH - 1);
    int ay1 = min(ay0 + 1, HH - 1);
    float a00 = pa[ay0 * WW + ax0], a01 = pa[ay0 * WW + ax1];
    float a10 = pa[ay1 * WW + ax0], a11 = pa[ay1 * WW + ax1];
    float ft = a00 * (1.0f - wxa) * (1.0f - wya) + a01 * wxa * (1.0f - wya)
             + a10 * (1.0f - wxa) * wya          + a11 * wxa * wya;

    // ---- F_b neighborhood: 12 deduped scalar loads ----
    const float* pb = Fb + (size_t)(b * CC + c) * (HH * WW);
    float gx0f = floorf(xs), gy0f = floorf(ys);
    float wx = xs - gx0f, wy = ys - gy0f;
    int x0 = min(max((int)gx0f, 0), WW - 1);
    int x1 = min(x0 + 1, WW - 1);
    int y0 = min(max((int)gy0f, 0), HH - 1);
    int y1 = min(y0 + 1, HH - 1);
    int xm = max(x0 - 1, 0), xp = min(x1 + 1, WW - 1);
    int ym = max(y0 - 1, 0), yp = min(y1 + 1, HH - 1);

    const float* r0 = pb + y0 * WW;
    const float* r1 = pb + y1 * WW;
    const float* rm = pb + ym * WW;
    const float* rp = pb + yp * WW;
    float vm0 = r0[xm], v00 = r0[x0], v01 = r0[x1], vp0 = r0[xp];
    float vm1 = r1[xm], v10 = r1[x0], v11 = r1[x1], vp1 = r1[xp];
    float um0 = rm[x0], um1 = rm[x1];
    float up0 = rp[x0], up1 = rp[x1];

    // Dedup: xq = max(x1-1,0) == x0 unless x1==x0 (then == xm). Same for rows.
    float vq0 = (x1 > x0) ? v00 : vm0;
    float vq1 = (x1 > x0) ? v10 : vm1;
    float uq0 = (y1 > y0) ? v00 : um0;
    float uq1 = (y1 > y0) ? v01 : um1;

    float w00 = (1.0f - wx) * (1.0f - wy);
    float w01 = wx * (1.0f - wy);
    float w10 = (1.0f - wx) * wy;
    float w11 = wx * wy;

    float fs = v00 * w00 + v01 * w01 + v10 * w10 + v11 * w11;

    float Jx = (0.5f * (v01 - vm0)) * w00 + (0.5f * (vp0 - vq0)) * w01
             + (0.5f * (v11 - vm1)) * w10 + (0.5f * (vp1 - vq1)) * w11;
    float Jy = (0.5f * (v10 - um0)) * w00 + (0.5f * (v11 - um1)) * w01
             + (0.5f * (up0 - uq0)) * w10 + (0.5f * (up1 - uq1)) * w11;

    // ---- 9 warp reductions over this 32-channel slice ----
    float sft2 = warp_sum(ft * ft);
    float sfs2 = warp_sum(fs * fs);
    float sjxx = warp_sum(Jx * Jx);
    float sjxy = warp_sum(Jx * Jy);
    float sjyy = warp_sum(Jy * Jy);
    float sjxfs = warp_sum(Jx * fs);
    float sjxft = warp_sum(Jx * ft);
    float sjyfs = warp_sum(Jy * fs);
    float sjyft = warp_sum(Jy * ft);

    if (lane == 0) {
        float4* dst = &g_part[(p * NSLICE + slice) * 3];
        dst[0] = make_float4(sft2, sfs2, sjxx, sjxy);
        dst[1] = make_float4(sjyy, sjxfs, sjxft, sjyfs);
        dst[2] = make_float4(sjyft, 0.0f, 0.0f, 0.0f);
    }

#if __CUDA_ARCH__ >= 900
    // Let the PDL-dependent stage-2 start its launch/prologue early.
    cudaTriggerProgrammaticLaunchCompletion();
#endif
}

// ---------------- Stage 2: combine slices, per-point solve, global sum ----------------
// Launched with programmatic stream serialization: blocks spawn while stage-1
// still runs, do stage-1-independent work, then cudaGridDependencySynchronize()
// blocks until stage-1's grid completes and its writes are visible.
// Grid: S2_BLOCKS blocks x 32 threads (single warp); thread t handles
// point p = bid*32 + t. No __syncthreads needed — shuffle-only reductions.
__global__ __launch_bounds__(32) void gnloss_stage2(
    const float* __restrict__ noise, float* __restrict__ out)
{
    const int lane = threadIdx.x;
    const int p = blockIdx.x * 32 + lane;

    // Independent of stage-1: issue before the dependency sync.
    const float2 nzv = ((const float2*)noise)[p];

#if __CUDA_ARCH__ >= 900
    cudaGridDependencySynchronize();
#endif

    float sft2 = 0, sfs2 = 0, sjxx = 0, sjxy = 0, sjyy = 0;
    float sjxfs = 0, sjxft = 0, sjyfs = 0, sjyft = 0;
#pragma unroll
    for (int s = 0; s < NSLICE; s++) {
        const float4* src = &g_part[(p * NSLICE + s) * 3];
        float4 q0 = src[0], q1 = src[1], q2 = src[2];
        sft2 += q0.x;  sfs2 += q0.y;  sjxx += q0.z;  sjxy += q0.w;
        sjyy += q1.x;  sjxfs += q1.y; sjxft += q1.z; sjyfs += q1.w;
        sjyft += q2.x;
    }

    float nt = fmaxf(sqrtf(sft2), 1e-12f);
    float ns = fmaxf(sqrtf(sfs2), 1e-12f);

    const float EPSF = 1e-9f;
    float A  = sjxx + EPSF;
    float Bo = sjxy;
    float D  = sjyy + EPSF;
    float b0 = sjxfs / ns - sjxft / nt;
    float b1 = sjyfs / ns - sjyft / nt;
    float det = A * D - Bo * Bo;
    float inv = 1.0f / det;
    float h0 = (D * b0 - Bo * b1) * inv;
    float h1 = (A * b1 - Bo * b0) * inv;
    // diff = ub - miu = (1 - 2*noise) + Hinv@b
    float d0 = (1.0f - 2.0f * nzv.x) + h0;
    float d1 = (1.0f - 2.0f * nzv.y) + h1;
    float e1 = 0.5f * (A * d0 * d0 + 2.0f * Bo * d0 * d1 + D * d1 * d1);
    float ld = logf(det);

    // ---- warp reduction in double (fixed order -> deterministic) ----
    double we1 = warp_sum_d((double)e1);
    double wld = warp_sum_d((double)ld);

    __shared__ unsigned s_last;
    if (lane == 0) {
        g_bp_e1[blockIdx.x] = we1;
        g_bp_ld[blockIdx.x] = wld;
        __threadfence();
        unsigned prev = atomicAdd(&g_count, 1u);
        s_last = (prev == (unsigned)(S2_BLOCKS - 1)) ? 1u : 0u;
    }
    __syncwarp();
    unsigned last = s_last;
    __syncwarp();

    if (last) {
        __threadfence();
        // 128 per-block partials: lane reads 4, fixed order, shuffle-reduce.
        double a1 = 0.0, a2 = 0.0;
#pragma unroll
        for (int k = 0; k < S2_BLOCKS / 32; k++) {
            int i = k * 32 + lane;
            a1 += g_bp_e1[i];
            a2 += g_bp_ld[i];
        }
        a1 = warp_sum_d(a1);
        a2 = warp_sum_d(a2);
        if (lane == 0) {
            double e1s = a1;
            double e2 = (double)NPTS * log(2.0 * M_PI) - 0.5 * a2;
            double e  = e1s + (2.0 / 7.0) * e2;
            out[0] = (float)(0.3 * e);
            out[1] = (float)e1s;
            out[2] = (float)e2;
            g_count = 0;   // reset for next graph replay
        }
    }
}

extern "C" void kernel_launch(void* const* d_in, const int* in_sizes, int n_in,
                              void* d_out, int out_size)
{
    const float* Fa    = (const float*)d_in[0];
    const float* Fb    = (const float*)d_in[1];
    const float* ma    = (const float*)d_in[2];
    const float* mb    = (const float*)d_in[3];
    const float* noise = (const float*)d_in[4];
    float* out = (float*)d_out;

    gnloss_stage1<<<NSLICE * (NPTS / 4), 128>>>(Fa, Fb, ma, mb, noise);

    // Stage-2 with programmatic dependent launch: overlap its launch/prologue
    // with stage-1 execution; cudaGridDependencySynchronize() in the kernel
    // provides the ordering on g_part.
    cudaLaunchConfig_t cfg = {};
    cfg.gridDim  = dim3(S2_BLOCKS, 1, 1);
    cfg.blockDim = dim3(32, 1, 1);
    cfg.dynamicSmemBytes = 0;
    cfg.stream = 0;   // same (legacy default) stream as stage-1
    cudaLaunchAttribute attrs[1];
    attrs[0].id = cudaLaunchAttributeProgrammaticStreamSerialization;
    attrs[0].val.programmaticStreamSerializationAllowed = 1;
    cfg.attrs = attrs;
    cfg.numAttrs = 1;
    cudaLaunchKernelEx(&cfg, gnloss_stage2, noise, (float*)d_out);
}

// round 11
// speedup vs baseline: 1.0468x; 1.0468x over previous
#include <cuda_runtime.h>
#include <math.h>

// Problem constants
#define BB 4
#define CC 128
#define HH 240
#define WW 320
#define NN 1024
#define NPTS (BB * NN)
#define NSLICE 4
#define SLICE_C 32          // channels per slice
#define S2_BLOCKS 128       // stage-2: 128 blocks x 32 threads, 1 point/thread

// Partials as 3 float4 "planes", each plane laid out [slice][point]:
// index (j*NSLICE + s)*NPTS + p.  Stage-1 store: 3 STG.128 from lane 0
// (same as AoS); stage-2 read: consecutive lanes -> consecutive points ->
// fully coalesced LDG.128.
__device__ float4 g_ps[3 * NSLICE * NPTS];
// Per-block partials for the final sum (S2_BLOCKS stage-2 blocks)
__device__ double g_bp_e1[S2_BLOCKS];
__device__ double g_bp_ld[S2_BLOCKS];
__device__ unsigned int g_count = 0;

__device__ __forceinline__ float warp_sum(float v) {
#pragma unroll
    for (int o = 16; o; o >>= 1) v += __shfl_xor_sync(0xffffffffu, v, o);
    return v;
}

__device__ __forceinline__ double warp_sum_d(double v) {
#pragma unroll
    for (int o = 16; o; o >>= 1) v += __shfl_xor_sync(0xffffffffu, v, o);
    return v;
}

// i is warp-uniform (0..3)
__device__ __forceinline__ float pick4(float4 v, int i) {
    float r = v.x;
    if (i == 1) r = v.y;
    else if (i == 2) r = v.z;
    else if (i == 3) r = v.w;
    return r;
}
// i is warp-uniform (0..7)
__device__ __forceinline__ float pick8(float4 a, float4 b, int i) {
    return (i < 4) ? pick4(a, i) : pick4(b, i - 4);
}

// ---------------- Stage 1: gather + per-(point,slice) partial sums ----------------
// Grid: NSLICE * (NPTS/4) blocks of 128 threads, slice-major.
// Block handles 4 points x one 32-channel slice; each warp owns one point.
__global__ __launch_bounds__(128) void gnloss_stage1(
    const float* __restrict__ Fa, const float* __restrict__ Fb,
    const float* __restrict__ ma, const float* __restrict__ mb,
    const float* __restrict__ noise)
{
    const int bid   = blockIdx.x;
    const int slice = bid >> 10;           // 0..3  (slice-major ordering)
    const int pg    = bid & 1023;          // point group
    const int w     = threadIdx.x >> 5;
    const int lane  = threadIdx.x & 31;
    const int p     = pg * 4 + w;          // point 0..4095
    const int b     = p >> 10;
    const int c     = slice * SLICE_C + lane;

    const float invL = 1.0f / 8.0f;
    const float2 mav = ((const float2*)ma)[p];
    const float2 mbv = ((const float2*)mb)[p];
    const float2 nzv = ((const float2*)noise)[p];
    const float xa = mav.x * invL, ya = mav.y * invL;
    const float xs = 2.0f * nzv.x - 1.0f + mbv.x * invL;
    const float ys = 2.0f * nzv.y - 1.0f + mbv.y * invL;

    // ---- f_t: bilinear sample of F_a (4 scalar LDG) ----
    const float* pa = Fa + (size_t)(b * CC + c) * (HH * WW);
    float fx0 = floorf(xa), fy0 = floorf(ya);
    float wxa = xa - fx0,  wya = ya - fy0;
    int ax0 = min(max((int)fx0, 0), WW - 1);
    int ax1 = min(ax0 + 1, WW - 1);
    int ay0 = min(max((int)fy0, 0), HH - 1);
    int ay1 = min(ay0 + 1, HH - 1);
    float a00 = pa[ay0 * WW + ax0], a01 = pa[ay0 * WW + ax1];
    float a10 = pa[ay1 * WW + ax0], a11 = pa[ay1 * WW + ax1];
    float ft = a00 * (1.0f - wxa) * (1.0f - wya) + a01 * wxa * (1.0f - wya)
             + a10 * (1.0f - wxa) * wya          + a11 * wxa * wya;

    // ---- F_b neighborhood ----
    const float* pb = Fb + (size_t)(b * CC + c) * (HH * WW);
    float gx0f = floorf(xs), gy0f = floorf(ys);
    float wx = xs - gx0f, wy = ys - gy0f;
    int x0 = min(max((int)gx0f, 0), WW - 1);
    int x1 = min(x0 + 1, WW - 1);
    int y0 = min(max((int)gy0f, 0), HH - 1);
    int y1 = min(y0 + 1, HH - 1);
    int xm = max(x0 - 1, 0), xp = min(x1 + 1, WW - 1);
    int ym = max(y0 - 1, 0), yp = min(y1 + 1, HH - 1);

    const float* r0 = pb + y0 * WW;
    const float* r1 = pb + y1 * WW;
    const float* rm = pb + ym * WW;
    const float* rp = pb + yp * WW;

    // Rows y0/y1 vectorized: xm..xp lie inside two aligned float4s at
    // base4 = min(xm & ~3, W-8); xp - base4 <= 7 in every clamp case.
    int base4 = min(xm & ~3, WW - 8);
    int im = xm - base4, i0 = x0 - base4, i1 = x1 - base4, ip = xp - base4;
    const float4* q0 = (const float4*)(r0 + base4);
    const float4* q1 = (const float4*)(r1 + base4);
    float4 q0a = q0[0], q0b = q0[1];
    float4 q1a = q1[0], q1b = q1[1];
    float vm0 = pick8(q0a, q0b, im), v00 = pick8(q0a, q0b, i0);
    float v01 = pick8(q0a, q0b, i1), vp0 = pick8(q0a, q0b, ip);
    float vm1 = pick8(q1a, q1b, im), v10 = pick8(q1a, q1b, i0);
    float v11 = pick8(q1a, q1b, i1), vp1 = pick8(q1a, q1b, ip);

    // Rows ym/yp scalar (2 each)
    float um0 = rm[x0], um1 = rm[x1];
    float up0 = rp[x0], up1 = rp[x1];

    // Dedup: xq = max(x1-1,0) == x0 unless x1==x0 (then == xm). Same for rows.
    float vq0 = (x1 > x0) ? v00 : vm0;
    float vq1 = (x1 > x0) ? v10 : vm1;
    float uq0 = (y1 > y0) ? v00 : um0;
    float uq1 = (y1 > y0) ? v01 : um1;

    float w00 = (1.0f - wx) * (1.0f - wy);
    float w01 = wx * (1.0f - wy);
    float w10 = (1.0f - wx) * wy;
    float w11 = wx * wy;

    float fs = v00 * w00 + v01 * w01 + v10 * w10 + v11 * w11;

    float Jx = (0.5f * (v01 - vm0)) * w00 + (0.5f * (vp0 - vq0)) * w01
             + (0.5f * (v11 - vm1)) * w10 + (0.5f * (vp1 - vq1)) * w11;
    float Jy = (0.5f * (v10 - um0)) * w00 + (0.5f * (v11 - um1)) * w01
             + (0.5f * (up0 - uq0)) * w10 + (0.5f * (up1 - uq1)) * w11;

    // ---- 9 warp reductions over this 32-channel slice ----
    float sft2 = warp_sum(ft * ft);
    float sfs2 = warp_sum(fs * fs);
    float sjxx = warp_sum(Jx * Jx);
    float sjxy = warp_sum(Jx * Jy);
    float sjyy = warp_sum(Jy * Jy);
    float sjxfs = warp_sum(Jx * fs);
    float sjxft = warp_sum(Jx * ft);
    float sjyfs = warp_sum(Jy * fs);
    float sjyft = warp_sum(Jy * ft);

    if (lane == 0) {
        g_ps[(0 * NSLICE + slice) * NPTS + p] = make_float4(sft2, sfs2, sjxx, sjxy);
        g_ps[(1 * NSLICE + slice) * NPTS + p] = make_float4(sjyy, sjxfs, sjxft, sjyfs);
        g_ps[(2 * NSLICE + slice) * NPTS + p] = make_float4(sjyft, 0.0f, 0.0f, 0.0f);
    }
}

// ---------------- Stage 2: combine slices, per-point solve, global sum ----------------
// Grid: S2_BLOCKS blocks x 32 threads (single warp); thread t handles
// point p = bid*32 + t. Reads are fully coalesced (consecutive lanes ->
// consecutive points within each [j][slice] plane).
__global__ __launch_bounds__(32) void gnloss_stage2(
    const float* __restrict__ noise, float* __restrict__ out)
{
    const int lane = threadIdx.x;
    const int p = blockIdx.x * 32 + lane;

    float sft2 = 0, sfs2 = 0, sjxx = 0, sjxy = 0, sjyy = 0;
    float sjxfs = 0, sjxft = 0, sjyfs = 0, sjyft = 0;
#pragma unroll
    for (int s = 0; s < NSLICE; s++) {
        float4 q0 = g_ps[(0 * NSLICE + s) * NPTS + p];
        float4 q1 = g_ps[(1 * NSLICE + s) * NPTS + p];
        float4 q2 = g_ps[(2 * NSLICE + s) * NPTS + p];
        sft2 += q0.x;  sfs2 += q0.y;  sjxx += q0.z;  sjxy += q0.w;
        sjyy += q1.x;  sjxfs += q1.y; sjxft += q1.z; sjyfs += q1.w;
        sjyft += q2.x;
    }

    const float2 nzv = ((const float2*)noise)[p];
    float nt = fmaxf(sqrtf(sft2), 1e-12f);
    float ns = fmaxf(sqrtf(sfs2), 1e-12f);

    const float EPSF = 1e-9f;
    float A  = sjxx + EPSF;
    float Bo = sjxy;
    float D  = sjyy + EPSF;
    float b0 = sjxfs / ns - sjxft / nt;
    float b1 = sjyfs / ns - sjyft / nt;
    float det = A * D - Bo * Bo;
    float inv = 1.0f / det;
    float h0 = (D * b0 - Bo * b1) * inv;
    float h1 = (A * b1 - Bo * b0) * inv;
    // diff = ub - miu = (1 - 2*noise) + Hinv@b
    float d0 = (1.0f - 2.0f * nzv.x) + h0;
    float d1 = (1.0f - 2.0f * nzv.y) + h1;
    float e1 = 0.5f * (A * d0 * d0 + 2.0f * Bo * d0 * d1 + D * d1 * d1);
    float ld = logf(det);

    // ---- warp reduction in double (fixed order -> deterministic) ----
    double we1 = warp_sum_d((double)e1);
    double wld = warp_sum_d((double)ld);

    __shared__ unsigned s_last;
    if (lane == 0) {
        g_bp_e1[blockIdx.x] = we1;
        g_bp_ld[blockIdx.x] = wld;
        __threadfence();
        unsigned prev = atomicAdd(&g_count, 1u);
        s_last = (prev == (unsigned)(S2_BLOCKS - 1)) ? 1u : 0u;
    }
    __syncwarp();
    unsigned last = s_last;
    __syncwarp();

    if (last) {
        __threadfence();
        // 128 per-block partials: lane reads 4, fixed order, shuffle-reduce.
        double a1 = 0.0, a2 = 0.0;
#pragma unroll
        for (int k = 0; k < S2_BLOCKS / 32; k++) {
            int i = k * 32 + lane;
            a1 += g_bp_e1[i];
            a2 += g_bp_ld[i];
        }
        a1 = warp_sum_d(a1);
        a2 = warp_sum_d(a2);
        if (lane == 0) {
            double e1s = a1;
            double e2 = (double)NPTS * log(2.0 * M_PI) - 0.5 * a2;
            double e  = e1s + (2.0 / 7.0) * e2;
            out[0] = (float)(0.3 * e);
            out[1] = (float)e1s;
            out[2] = (float)e2;
            g_count = 0;   // reset for next graph replay
        }
    }
}

extern "C" void kernel_launch(void* const* d_in, const int* in_sizes, int n_in,
                              void* d_out, int out_size)
{
    const float* Fa    = (const float*)d_in[0];
    const float* Fb    = (const float*)d_in[1];
    const float* ma    = (const float*)d_in[2];
    const float* mb    = (const float*)d_in[3];
    const float* noise = (const float*)d_in[4];
    float* out = (float*)d_out;

    gnloss_stage1<<<NSLICE * (NPTS / 4), 128>>>(Fa, Fb, ma, mb, noise);
    gnloss_stage2<<<S2_BLOCKS, 32>>>(noise, out);
}